// round 17
// baseline (speedup 1.0000x reference)
#include <cuda_runtime.h>
#include <cuda.h>
#include <cstdint>

// Problem dims (fixed)
#define NB   256
#define LL   2048
#define QK   512
#define HH   128

#define TILE_ROWS 128
#define SPLITS    16                        // per batch
#define NCTAS     2048                      // each CTA: 2 tiles = 256 rows
#define KCHUNK    32
#define NCH       32                        // 2 tiles x 16 K32-chunks
#define THREADS   256
#define NSTAGE    3

#define A_STAGE_BYTES 16384                 // 128 rows x 128B
#define B_STAGE_BYTES 16384
#define STAGE_TX      (A_STAGE_BYTES + B_STAGE_BYTES)

// smem byte offsets
#define SM_A     0
#define SM_B     (NSTAGE * A_STAGE_BYTES)              // 49152
#define SM_QS    (SM_B + NSTAGE * B_STAGE_BYTES)       // 98304
#define SM_VAS   (SM_QS + 512)                         // 98816
#define SM_ES4   (SM_VAS + 512)                        // 99328: 4 x 128 floats
#define SM_PS    (SM_ES4 + 2048)                       // 101376 (reused per tile)
#define SM_RED   (SM_PS + 512)                         // 101888
#define SM_CST   (SM_RED + 128)                        // 102016
#define SM_MBAR  (SM_CST + 2048)                       // 104064: full[3] + empty[3]
#define SM_TOTAL (SM_MBAR + 64)                        // ~101.7 KB -> 2 CTAs/SM

// ---------------- device scratch ----------------
__device__ float g_q[NB * HH];              // q = Wa @ last_hidden
__device__ float g_p[NB * LL];
__device__ float g_pz[NB * SPLITS];
__device__ float g_pc[(size_t)NB * SPLITS * QK];
__device__ int   g_cnt[NB];                 // zero-init; self-resetting

// ---------------- helpers ----------------
__device__ __forceinline__ void mbar_init(uint32_t a, uint32_t cnt) {
    asm volatile("mbarrier.init.shared.b64 [%0], %1;" :: "r"(a), "r"(cnt) : "memory");
}
__device__ __forceinline__ void mbar_expect_tx(uint32_t a, uint32_t bytes) {
    asm volatile("mbarrier.arrive.expect_tx.shared.b64 _, [%0], %1;" :: "r"(a), "r"(bytes) : "memory");
}
__device__ __forceinline__ void mbar_arrive(uint32_t a) {
    asm volatile("mbarrier.arrive.shared.b64 _, [%0];" :: "r"(a) : "memory");
}
__device__ __forceinline__ void mbar_wait(uint32_t a, uint32_t par) {
    asm volatile(
        "{\n\t.reg .pred P1;\n"
        "WAIT_LOOP_%=:\n\t"
        "mbarrier.try_wait.parity.acquire.cta.shared::cta.b64 P1, [%0], %1, 0x989680;\n\t"
        "@P1 bra.uni WAIT_DONE_%=;\n\t"
        "bra.uni WAIT_LOOP_%=;\n"
        "WAIT_DONE_%=:\n\t}"
        :: "r"(a), "r"(par) : "memory");
}
__device__ __forceinline__ void tma2d(uint32_t dst, const CUtensorMap* m, int x, int y, uint32_t bar) {
    asm volatile(
        "cp.async.bulk.tensor.2d.shared::cta.global.tile.mbarrier::complete_tx::bytes "
        "[%0], [%1, {%2, %3}], [%4];"
        :: "r"(dst), "l"(m), "r"(x), "r"(y), "r"(bar) : "memory");
}
__device__ __forceinline__ void mma_tf32(float* c, const uint32_t* a, const uint32_t* b) {
    asm volatile(
        "mma.sync.aligned.m16n8k8.row.col.f32.tf32.tf32.f32 "
        "{%0,%1,%2,%3},{%4,%5,%6,%7},{%8,%9},{%0,%1,%2,%3};"
        : "+f"(c[0]), "+f"(c[1]), "+f"(c[2]), "+f"(c[3])
        : "r"(a[0]), "r"(a[1]), "r"(a[2]), "r"(a[3]), "r"(b[0]), "r"(b[1]));
}
__device__ __forceinline__ void ldsm_x4(uint32_t& r0, uint32_t& r1, uint32_t& r2, uint32_t& r3,
                                        uint32_t addr) {
    asm volatile("ldmatrix.sync.aligned.m8n8.x4.shared.b16 {%0,%1,%2,%3}, [%4];"
                 : "=r"(r0), "=r"(r1), "=r"(r2), "=r"(r3) : "r"(addr));
}
__device__ __forceinline__ float tanh_fast(float x) {
    float y; asm("tanh.approx.f32 %0, %1;" : "=f"(y) : "f"(x)); return y;
}

// ---------------- kernel 0: q projection (coalesced, warp-per-rows) ----------------
__global__ void __launch_bounds__(512)
k_qproj(const float* __restrict__ last_hidden, const float* __restrict__ Wa) {
    const int n    = blockIdx.x;
    const int warp = threadIdx.x >> 5;
    const int lane = threadIdx.x & 31;

    const float4* x4 = reinterpret_cast<const float4*>(last_hidden + (size_t)n * QK);
    float4 xv[4];
#pragma unroll
    for (int k = 0; k < 4; ++k) xv[k] = x4[lane + k * 32];

#pragma unroll
    for (int rr = 0; rr < 8; ++rr) {
        const int h = warp * 8 + rr;
        const float4* w4 = reinterpret_cast<const float4*>(Wa + (size_t)h * QK);
        float a = 0.f;
#pragma unroll
        for (int k = 0; k < 4; ++k) {
            float4 w = w4[lane + k * 32];
            a += w.x * xv[k].x + w.y * xv[k].y + w.z * xv[k].z + w.w * xv[k].w;
        }
#pragma unroll
        for (int o = 16; o > 0; o >>= 1) a += __shfl_xor_sync(0xffffffffu, a, o);
        if (lane == 0) g_q[n * HH + h] = a;
    }
}

// ---------------- kernel 1: persistent 2-tile, immediate symmetric tail ----------------
__global__ void __launch_bounds__(THREADS, 2)
k_fused(const __grid_constant__ CUtensorMap tmA,   // X tiles, SW128
        const __grid_constant__ CUtensorMap tmB,   // Ua tiles, SW128
        const float* __restrict__ X,               // (NB,LL,QK) for context re-read
        const float* __restrict__ va,              // (1,HH)
        float* __restrict__ out) {
    extern __shared__ __align__(1024) char sm[];
    const uint32_t su = (uint32_t)__cvta_generic_to_shared(sm);
    float* qs  = reinterpret_cast<float*>(sm + SM_QS);
    float* vas = reinterpret_cast<float*>(sm + SM_VAS);
    float* es4 = reinterpret_cast<float*>(sm + SM_ES4);
    float* ps  = reinterpret_cast<float*>(sm + SM_PS);
    float* red = reinterpret_cast<float*>(sm + SM_RED);
    float* cst = reinterpret_cast<float*>(sm + SM_CST);
    __shared__ int s_last;

    const int tid  = threadIdx.x;
    const int bx   = blockIdx.x;
    const int rowA = bx * 256;                 // tile0 rows [rowA, rowA+128)
    const int n    = bx >> 3;                  // batch
    const int sx0  = bx * 2;                   // global split of tile0

    const int warp = tid >> 5;
    const int lane = tid & 31;
    const int wr = warp >> 2;          // 0..1 : 64-row strip
    const int wc = warp & 3;           // 0..3 : 32-col strip
    const int g  = lane >> 2;
    const int t  = lane & 3;

    // ldmatrix per-lane addressing (16B segments, SW128-swizzled rows)
    const int swz   = (lane & 7) << 4;
    const int rowAa = lane & 15;
    const int hiA   = (lane >> 4) << 4;
    const int rowBb = (lane & 7) + ((lane >> 4) << 3);
    const int hiB   = ((lane >> 3) & 1) << 4;

    const uint32_t mbf = su + SM_MBAR;        // full[s] at +s*8
    const uint32_t mbe = su + SM_MBAR + 24;   // empty[s] at +s*8

    if (tid == 0) {
#pragma unroll
        for (int s = 0; s < NSTAGE; ++s) {
            mbar_init(mbf + s * 8, 1);
            mbar_init(mbe + s * 8, 8);
        }
    }
    if (tid < HH) {
        vas[tid] = va[tid];
        qs[tid]  = g_q[n * HH + tid];
    }
    __syncthreads();

    // prologue: fill all 3 stages
    if (tid == 0) {
#pragma unroll
        for (int c = 0; c < NSTAGE; ++c) {
            mbar_expect_tx(mbf + c * 8, STAGE_TX);
            tma2d(su + SM_A + c * A_STAGE_BYTES, &tmA, c * KCHUNK, rowA, mbf + c * 8);
            tma2d(su + SM_B + c * B_STAGE_BYTES, &tmB, c * KCHUNK, 0, mbf + c * 8);
        }
    }

    float acc[4][4][4];
#pragma unroll
    for (int m = 0; m < 4; ++m)
#pragma unroll
        for (int j = 0; j < 4; ++j)
#pragma unroll
            for (int c = 0; c < 4; ++c) acc[m][j][c] = 0.f;

    const uint32_t aBase0 = su + SM_A + (uint32_t)((wr * 64 + rowAa) * 128);
    const uint32_t bBase0 = su + SM_B + (uint32_t)((wc * 32 + rowBb) * 128);

    // one chunk; s is a literal at every call site
    auto do_chunk = [&](int kc, const int s, uint32_t phase) __attribute__((always_inline)) {
        if (tid == 0 && kc >= 1 && kc + 2 < NCH) {
            const int c  = kc + 2;
            const int ns = (s + 2 >= NSTAGE) ? (s - 1) : (s + 2);   // literal
            mbar_wait(mbe + ns * 8, (uint32_t)(((c - NSTAGE) / NSTAGE) & 1));
            mbar_expect_tx(mbf + ns * 8, STAGE_TX);
            tma2d(su + SM_A + ns * A_STAGE_BYTES, &tmA, (c & 15) * KCHUNK,
                  rowA + ((c >> 4) << 7), mbf + ns * 8);
            tma2d(su + SM_B + ns * B_STAGE_BYTES, &tmB, (c & 15) * KCHUNK, 0, mbf + ns * 8);
        }

        mbar_wait(mbf + s * 8, phase);

        const uint32_t abase = aBase0 + (uint32_t)(s * A_STAGE_BYTES);
        const uint32_t bbase = bBase0 + (uint32_t)(s * B_STAGE_BYTES);

#pragma unroll
        for (int ks = 0; ks < 4; ++ks) {
            const uint32_t colA = (uint32_t)((ks * 32 + hiA) ^ swz);
            const uint32_t colB = (uint32_t)((ks * 32 + hiB) ^ swz);

            uint32_t bu[4][2];
#pragma unroll
            for (int jj = 0; jj < 2; ++jj) {
                ldsm_x4(bu[2*jj][0], bu[2*jj][1], bu[2*jj+1][0], bu[2*jj+1][1],
                        bbase + (uint32_t)(jj * 16 * 128) + colB);
            }
#pragma unroll
            for (int m = 0; m < 4; ++m) {
                uint32_t au[4];
                ldsm_x4(au[0], au[1], au[2], au[3],
                        abase + (uint32_t)(m * 16 * 128) + colA);
#pragma unroll
                for (int j = 0; j < 4; ++j) mma_tf32(acc[m][j], au, bu[j]);
            }
        }
        if (lane == 0) mbar_arrive(mbe + s * 8);
    };

    // full tile tail: epilogue + softmax + immediate context + fan-in
    auto do_tail = [&](int rowT, int sxi, bool is_last) __attribute__((always_inline)) {
#pragma unroll
        for (int m = 0; m < 4; ++m) {
#pragma unroll
            for (int rr = 0; rr < 2; ++rr) {
                float pa = 0.f;
#pragma unroll
                for (int j = 0; j < 4; ++j) {
#pragma unroll
                    for (int cc = 0; cc < 2; ++cc) {
                        int h = wc * 32 + j * 8 + t * 2 + cc;
                        pa += vas[h] * tanh_fast(qs[h] + acc[m][j][rr * 2 + cc]);
                    }
                }
                pa += __shfl_xor_sync(0xffffffffu, pa, 1);
                pa += __shfl_xor_sync(0xffffffffu, pa, 2);
                if (t == 0) es4[wc * 128 + wr * 64 + m * 16 + rr * 8 + g] = pa;
#pragma unroll
                for (int j = 0; j < 4; ++j)
#pragma unroll
                    for (int cc = 0; cc < 2; ++cc)
                        acc[m][j][rr * 2 + cc] = 0.f;
            }
        }
        __syncthreads();

        // energies bounded (|e| <= sum|va| ~= 11): exp without max-pass is safe
        if (tid < TILE_ROWS) {
            float e = es4[tid] + es4[128 + tid] + es4[256 + tid] + es4[384 + tid];
            float p = __expf(e);
            ps[tid] = p;
            g_p[rowT + tid] = p;
            float sZ = p;
#pragma unroll
            for (int o = 16; o > 0; o >>= 1) sZ += __shfl_xor_sync(0xffffffffu, sZ, o);
            if (lane == 0) red[warp] = sZ;
        }
        __syncthreads();
        if (tid == 0)
            g_pz[sxi] = red[0] + red[1] + red[2] + red[3];
        // ps visible after the sync above

        // immediate context (X tile still L2-hot)
        {
            const int c4 = (tid & 127) * 4;
            const int half = tid >> 7;
            const float* Xp = X + (size_t)(rowT + half * 64) * QK + c4;
            float4 a = make_float4(0.f, 0.f, 0.f, 0.f);
#pragma unroll 8
            for (int l = 0; l < 64; ++l) {
                float pl = ps[half * 64 + l];
                float4 x = *reinterpret_cast<const float4*>(Xp + (size_t)l * QK);
                a.x += pl * x.x; a.y += pl * x.y; a.z += pl * x.z; a.w += pl * x.w;
            }
            if (half == 1) *reinterpret_cast<float4*>(cst + c4) = a;
            __syncthreads();
            if (half == 0) {
                float4 b = *reinterpret_cast<const float4*>(cst + c4);
                a.x += b.x; a.y += b.y; a.z += b.z; a.w += b.w;
                *reinterpret_cast<float4*>(&g_pc[(size_t)sxi * QK + c4]) = a;
            }
        }
        __syncthreads();

        if (tid == 0) {
            __threadfence();
            int old = atomicAdd(&g_cnt[n], 1);
            s_last = (is_last && old == SPLITS - 1) ? 1 : 0;
        }
        __syncthreads();
        if (is_last && s_last) {
            __threadfence();
            float Z = 0.f;
#pragma unroll
            for (int i = 0; i < SPLITS; ++i) Z += g_pz[n * SPLITS + i];
            const float rZ = 1.f / Z;

            float* ctx = out;                       // (NB, QK)
            float* wts = out + (size_t)NB * QK;     // (NB, LL)
            if (tid < 128) {                        // 128 float4 slots cover QK
                float4 c = make_float4(0.f, 0.f, 0.f, 0.f);
#pragma unroll
                for (int i = 0; i < SPLITS; ++i) {
                    float4 v = *reinterpret_cast<const float4*>(
                        &g_pc[(size_t)(n * SPLITS + i) * QK + tid * 4]);
                    c.x += v.x; c.y += v.y; c.z += v.z; c.w += v.w;
                }
                c.x *= rZ; c.y *= rZ; c.z *= rZ; c.w *= rZ;
                *reinterpret_cast<float4*>(&ctx[(size_t)n * QK + tid * 4]) = c;
            }
#pragma unroll
            for (int i = 0; i < 2; ++i) {           // 512 float4 slots cover LL
                int l4 = tid + i * THREADS;
                float4 p4 = *reinterpret_cast<const float4*>(&g_p[(size_t)n * LL + l4 * 4]);
                p4.x *= rZ; p4.y *= rZ; p4.z *= rZ; p4.w *= rZ;
                *reinterpret_cast<float4*>(&wts[(size_t)n * LL + l4 * 4]) = p4;
            }
            if (tid == 0) g_cnt[n] = 0;   // self-reset for next replay
        }
    };

    // ---- tile 0: chunks 0..15 (literal stage triples) ----
#pragma unroll 1
    for (int kp = 0; kp < 15; kp += 3) {
        const uint32_t ph = (uint32_t)((kp / 3) & 1);
        do_chunk(kp + 0, 0, ph);
        do_chunk(kp + 1, 1, ph);
        do_chunk(kp + 2, 2, ph);
    }
    do_chunk(15, 0, 1u);

    // ---- tile0 tail; TMA for chunks 16,17 (issued at kc=14,15) rides through it ----
    do_tail(rowA, sx0, false);

    // ---- tile 1: chunks 16..31 ----
    do_chunk(16, 1, 1u);
    do_chunk(17, 2, 1u);
#pragma unroll 1
    for (int kp = 18; kp < 30; kp += 3) {
        const uint32_t ph = (uint32_t)((kp / 3) & 1);
        do_chunk(kp + 0, 0, ph);
        do_chunk(kp + 1, 1, ph);
        do_chunk(kp + 2, 2, ph);
    }
    do_chunk(30, 0, 0u);
    do_chunk(31, 1, 0u);

    // ---- tile1 tail (combine possible here only) ----
    do_tail(rowA + TILE_ROWS, sx0 + 1, true);
}

// ---------------- host: tensormap encode via runtime entry point (no -lcuda) ----------------
typedef CUresult (*tmap_encode_t)(
    CUtensorMap*, CUtensorMapDataType, cuuint32_t, void*,
    const cuuint64_t*, const cuuint64_t*, const cuuint32_t*, const cuuint32_t*,
    CUtensorMapInterleave, CUtensorMapSwizzle, CUtensorMapL2promotion, CUtensorMapFloatOOBfill);

extern "C" void kernel_launch(void* const* d_in, const int* in_sizes, int n_in,
                              void* d_out, int out_size) {
    const float* last_hidden     = (const float*)d_in[0];
    const float* encoder_outputs = (const float*)d_in[1];
    const float* Wa              = (const float*)d_in[2];
    const float* Ua              = (const float*)d_in[3];
    const float* va              = (const float*)d_in[4];
    float* out = (float*)d_out;

    static tmap_encode_t encode = nullptr;
    static bool attr_set = false;
    if (!attr_set) {
        cudaFuncSetAttribute(k_fused, cudaFuncAttributeMaxDynamicSharedMemorySize, SM_TOTAL);
        cudaDriverEntryPointQueryResult qr;
        void* fp = nullptr;
        cudaGetDriverEntryPoint("cuTensorMapEncodeTiled", &fp, cudaEnableDefault, &qr);
        encode = (tmap_encode_t)fp;
        attr_set = true;
    }

    CUtensorMap tmA, tmB;
    {
        cuuint64_t dims[2]   = {QK, (cuuint64_t)NB * LL};
        cuuint64_t stride[1] = {QK * sizeof(float)};
        cuuint32_t box[2]    = {KCHUNK, TILE_ROWS};
        cuuint32_t elems[2]  = {1, 1};
        encode(&tmA, CU_TENSOR_MAP_DATA_TYPE_FLOAT32, 2, (void*)encoder_outputs,
               dims, stride, box, elems,
               CU_TENSOR_MAP_INTERLEAVE_NONE, CU_TENSOR_MAP_SWIZZLE_128B,
               CU_TENSOR_MAP_L2_PROMOTION_L2_128B, CU_TENSOR_MAP_FLOAT_OOB_FILL_NONE);
    }
    {
        cuuint64_t dims[2]   = {QK, HH};
        cuuint64_t stride[1] = {QK * sizeof(float)};
        cuuint32_t box[2]    = {KCHUNK, HH};
        cuuint32_t elems[2]  = {1, 1};
        encode(&tmB, CU_TENSOR_MAP_DATA_TYPE_FLOAT32, 2, (void*)Ua,
               dims, stride, box, elems,
               CU_TENSOR_MAP_INTERLEAVE_NONE, CU_TENSOR_MAP_SWIZZLE_128B,
               CU_TENSOR_MAP_L2_PROMOTION_L2_128B, CU_TENSOR_MAP_FLOAT_OOB_FILL_NONE);
    }

    k_qproj<<<NB, 512>>>(last_hidden, Wa);
    k_fused<<<NCTAS, THREADS, SM_TOTAL>>>(tmA, tmB, encoder_outputs, va, out);
}